// round 9
// baseline (speedup 1.0000x reference)
#include <cuda_runtime.h>
#include <cuda_bf16.h>
#include <cstdint>

typedef unsigned long long ull;

// ---------------- problem constants ----------------
#define TT   256
#define BB   64
#define EE   512
#define HH   512
#define KK   32
#define TB   (TT*BB)        // 16384
#define NG   4096           // 2 dirs * 4H gate columns
#define STARTT 30
#define ENDT   31
#define NEGV  (-100000.0f)

#define HBYTES  (BB*HH*4)   // 131072
#define CHUNKB  8192        // 4 rows * 512 * 4B
#define WSTRIDE 514         // padded plane stride per k-quarter (slots)

// ---------------- device scratch (static, no cudaMalloc) ----------------
__device__ float g_xp[(size_t)TB * NG];        // reused by both layers
__device__ float g_h0[(size_t)TB * 1024];      // layer0 output (fwd|bwd)
__device__ float g_h1[(size_t)TB * 1024];      // layer1 output
__device__ float g_feats[(size_t)TB * KK];     // emissions
__device__ float g_hbuf[2 * 2 * BB * HH];      // [parity][dir][b][j]
__device__ float g_logz[BB];

// per-direction grid barrier state
__device__ unsigned g_cnt2[2] = {0, 0};
__device__ unsigned g_gen2[2] = {0, 0};

// ---------------- helpers ----------------
__device__ __forceinline__ void ffma2(ull &d, ull a, ull b) {
    asm("fma.rn.f32x2 %0, %1, %2, %0;" : "+l"(d) : "l"(a), "l"(b));
}
__device__ __forceinline__ float2 unpack2(ull v) {
    float2 r;
    asm("mov.b64 {%0, %1}, %2;" : "=f"(r.x), "=f"(r.y) : "l"(v));
    return r;
}
__device__ __forceinline__ ull pk2(float lo, float hi) {
    ull v;
    asm("mov.b64 %0, {%1,%2};" : "=l"(v) : "f"(lo), "f"(hi));
    return v;
}
__device__ __forceinline__ float sigmoidf_(float x) { return 1.0f / (1.0f + __expf(-x)); }

__device__ __forceinline__ uint32_t s2u(const void* p) {
    uint32_t a;
    asm("{ .reg .u64 t; cvta.to.shared.u64 t, %1; cvt.u32.u64 %0, t; }" : "=r"(a) : "l"(p));
    return a;
}
__device__ __forceinline__ void mwait(uint32_t mbar, uint32_t phase) {
    asm volatile(
        "{\n\t.reg .pred P;\n"
        "W%=:\n\t"
        "mbarrier.try_wait.parity.acquire.cta.shared::cta.b64 P, [%0], %1, 0x989680;\n\t"
        "@P bra D%=;\n\t"
        "bra W%=;\n"
        "D%=:\n\t}"
        :: "r"(mbar), "r"(phase) : "memory");
}

__device__ __forceinline__ void grid_barrier(int dir) {
    __syncthreads();
    if (threadIdx.x == 0) {
        __threadfence();
        unsigned my = *((volatile unsigned*)&g_gen2[dir]);
        if (atomicAdd(&g_cnt2[dir], 1u) == 63u) {
            g_cnt2[dir] = 0;
            __threadfence();
            *((volatile unsigned*)&g_gen2[dir]) = my + 1;
        } else {
            while (*((volatile unsigned*)&g_gen2[dir]) == my) { }
        }
        __threadfence();
    }
    __syncthreads();
}

// ---------------- SGEMM: C[16384][4096] = A[M][KD]*Bw[4096][KD]^T + bias ------
// 128x128 tile, 512 threads, f32x2. Loaders pack k-pairs in registers (STS.64,
// conflict-free 4*kp banking). Bs consumer XOR-swizzled -> conflict-free LDS.128.
template<int KD, bool GATHER>
__global__ __launch_bounds__(512) void k_gemm(
    const float* __restrict__ A, const int* __restrict__ tok,
    const float* __restrict__ Bw, const float* __restrict__ bias,
    float* __restrict__ C)
{
    __shared__ ull As[8 * 130];
    __shared__ ull Bs[8 * 130];
    int tid = threadIdx.x;
    int n0 = blockIdx.x * 128, m0 = blockIdx.y * 128;
    int tn = tid & 15, tm = tid >> 4;

    int kp = tid & 7, rr = tid >> 3;   // rr 0..63
    const float* aro[2];
    const float* bro[2];
    int sA[2], sB[2];
#pragma unroll
    for (int i = 0; i < 2; i++) {
        int r = rr + 64 * i;
        aro[i] = (GATHER ? A + (size_t)tok[m0 + r] * KD
                         : A + (size_t)(m0 + r) * KD) + 2 * kp;
        bro[i] = Bw + (size_t)(n0 + r) * KD + 2 * kp;
        sA[i] = kp * 130 + r;
        int t8 = r >> 3, j = (r >> 1) & 3, sw = (r >> 4) & 3;
        sB[i] = kp * 130 + (t8 * 4 + (j ^ sw)) * 2 + (r & 1);
    }

    float bb[8];
#pragma unroll
    for (int j = 0; j < 8; j++) bb[j] = bias[n0 + tn * 8 + j];

    ull acc[4][8];
#pragma unroll
    for (int i = 0; i < 4; i++)
#pragma unroll
        for (int j = 0; j < 8; j++) acc[i][j] = 0ull;

    float2 pa[2], pb[2];
#pragma unroll
    for (int i = 0; i < 2; i++) { pa[i] = *(const float2*)aro[i]; pb[i] = *(const float2*)bro[i]; }

    int swc = (tn >> 1) & 3;

    for (int k0 = 0; k0 < KD; k0 += 16) {
#pragma unroll
        for (int i = 0; i < 2; i++) {
            As[sA[i]] = pk2(pa[i].x, pa[i].y);
            Bs[sB[i]] = pk2(pb[i].x, pb[i].y);
        }
        __syncthreads();
        if (k0 + 16 < KD) {
#pragma unroll
            for (int i = 0; i < 2; i++) {
                pa[i] = *(const float2*)(aro[i] + k0 + 16);
                pb[i] = *(const float2*)(bro[i] + k0 + 16);
            }
        }
#pragma unroll
        for (int k2 = 0; k2 < 8; k2++) {
            ull a2[4], b2[8];
            {
                ulonglong2 v0 = *(const ulonglong2*)&As[k2 * 130 + tm * 4];
                ulonglong2 v1 = *(const ulonglong2*)&As[k2 * 130 + tm * 4 + 2];
                a2[0] = v0.x; a2[1] = v0.y; a2[2] = v1.x; a2[3] = v1.y;
            }
#pragma unroll
            for (int j = 0; j < 4; j++) {
                ulonglong2 v = *(const ulonglong2*)&Bs[k2 * 130 + (tn * 4 + (j ^ swc)) * 2];
                b2[2 * j] = v.x; b2[2 * j + 1] = v.y;
            }
#pragma unroll
            for (int i = 0; i < 4; i++)
#pragma unroll
                for (int j = 0; j < 8; j++)
                    ffma2(acc[i][j], a2[i], b2[j]);
        }
        __syncthreads();
    }
#pragma unroll
    for (int i = 0; i < 4; i++) {
        int m = m0 + tm * 4 + i;
        float o[8];
#pragma unroll
        for (int j = 0; j < 8; j++) {
            float2 u = unpack2(acc[i][j]);
            o[j] = u.x + u.y + bb[j];
        }
        *(float4*)&C[(size_t)m * NG + n0 + tn * 8]     = make_float4(o[0], o[1], o[2], o[3]);
        *(float4*)&C[(size_t)m * NG + n0 + tn * 8 + 4] = make_float4(o[4], o[5], o[6], o[7]);
    }
}

// ---------------- persistent BiLSTM layer kernel ----------------
// grid = 128 CTAs (1/SM), 512 threads (16 warps, 4/SMSP). CTA c: dir = c>>6,
// owns h-cols j0..j0+7. Warp w owns batch rows w*4..w*4+3 (one 8KB h-chunk,
// own mbarrier). Weight planes use PADDED per-k-quarter stride (514 slots,
// mod-8 phase 2) AND the per-k-quarter rotation swizzle on h so BOTH weight
// and h LDS.128 are bank-conflict-free. xp for the next step is prefetched
// before the grid barrier so the DRAM latency hides in the barrier wait.
__global__ __launch_bounds__(512) void k_lstm(
    const float* __restrict__ xp,   // [TB][4096]: dir*2048 + gt*512 + j (bias incl)
    const float* __restrict__ whh,  // raw [2][2048][512]
    float* __restrict__ hout)       // [TB][1024]: dir*512 + j
{
    extern __shared__ float sm[];
    float* h_s = sm;                                  // 32768 floats (128KB)
    ulonglong2* wA = (ulonglong2*)(sm + 32768);       // gates 0,1: 4*514 slots
    ulonglong2* wB = wA + 4 * WSTRIDE;                // gates 2,3: 4*514 slots
    ull* mbar = (ull*)(wB + 4 * WSTRIDE);             // 16 mbarriers

    int tid = threadIdx.x, cta = blockIdx.x;
    int dir = cta >> 6, j0 = (cta & 63) * 8;
    int lane = tid & 31, w = tid >> 5;                // 16 warps
    int c4 = lane & 7, ks = (lane >> 3) & 3;

    uint32_t mbar_u = s2u(mbar), hdst_u = s2u(h_s);
    if (tid < 16)
        asm volatile("mbarrier.init.shared.b64 [%0], 1;" :: "r"(mbar_u + tid * 8));

    // stage weights: slot (kq, k2, c4) -> kq*514 + k2*8 + c4 holds k-pair
    // kq*64 + ((k2 + 4*kq) & 63)  (rotation matched by consumer's q2).
    const float* W = whh + (size_t)dir * 2048 * 512;
    for (int f = tid; f < 2048; f += 512) {
        int fc = f & 7, k2 = (f >> 3) & 63, kq = f >> 9;
        int k2r = (k2 + 4 * kq) & 63;
        int k = kq * 128 + k2r * 2;
        int jc = j0 + fc;
        int slot = kq * WSTRIDE + k2 * 8 + fc;
        const float* w0 = W + (size_t)jc * 512 + k;            // gate 0 row jc
        ull a0 = pk2(w0[0],                 w0[1]);
        ull a1 = pk2(w0[512 * 512],         w0[512 * 512 + 1]);
        ull b0 = pk2(w0[1024 * 512],        w0[1024 * 512 + 1]);
        ull b1 = pk2(w0[1536 * 512],        w0[1536 * 512 + 1]);
        ulonglong2 va; va.x = a0; va.y = a1;
        ulonglong2 vb; vb.x = b0; vb.y = b1;
        wA[slot] = va;
        wB[slot] = vb;
    }
    __syncthreads();

    const ulonglong2* wAp = wA + ks * WSTRIDE + c4;
    const ulonglong2* wBp = wB + ks * WSTRIDE + c4;
    const float* hb = h_s + (w * 4) * 512 + ks * 128;
    int rot = ks * 4;

    float creg[4];
#pragma unroll
    for (int i = 0; i < 4; i++) creg[i] = 0.0f;

    // initial xp prefetch for s = 0
    float xcur[4][4];
    if (ks == 0) {
        int t0 = dir ? (TT - 1) : 0;
#pragma unroll
        for (int i = 0; i < 4; i++) {
            int b = w * 4 + i;
            const float* xr = xp + (size_t)(t0 * BB + b) * NG + dir * 2048 + j0 + c4;
            xcur[i][0] = xr[0];
            xcur[i][1] = xr[512];
            xcur[i][2] = xr[1024];
            xcur[i][3] = xr[1536];
        }
    }

    for (int s = 0; s < TT; s++) {
        int t = dir ? (TT - 1 - s) : s;
        int par = s & 1;

        // kick off 16 independent row-chunk copies (producer writes fenced by
        // the per-direction grid barrier at the end of the previous step)
        if (s > 0 && tid < 16) {
            const float* src = g_hbuf + (size_t)(par * 2 + dir) * BB * HH + tid * 2048;
            uint32_t mb = mbar_u + tid * 8;
            asm volatile("mbarrier.arrive.expect_tx.shared.b64 _, [%0], %1;"
                         :: "r"(mb), "r"((uint32_t)CHUNKB));
            asm volatile("cp.async.bulk.shared::cta.global.mbarrier::complete_tx::bytes [%0], [%1], %2, [%3];"
                         :: "r"(hdst_u + (uint32_t)tid * CHUNKB), "l"(src),
                            "r"((uint32_t)CHUNKB), "r"(mb) : "memory");
        }

        float af[4][4];
        if (s > 0) {
            // wait only for THIS warp's row chunk
            mwait(mbar_u + w * 8, (s - 1) & 1);

            ull acc[4][4];
#pragma unroll
            for (int i = 0; i < 4; i++)
#pragma unroll
                for (int g = 0; g < 4; g++) acc[i][g] = 0ull;

#pragma unroll 4
            for (int q = 0; q < 64; q += 2) {
                int q2 = (q + rot) & 63;     // rotated k-pair (matches staged weights)
                ulonglong2 wa0 = wAp[q * 8];
                ulonglong2 wb0 = wBp[q * 8];
                ulonglong2 wa1 = wAp[(q + 1) * 8];
                ulonglong2 wb1 = wBp[(q + 1) * 8];
#pragma unroll
                for (int i = 0; i < 4; i++) {
                    ulonglong2 h2 = *(const ulonglong2*)(hb + i * 512 + q2 * 2);
                    ffma2(acc[i][0], h2.x, wa0.x);
                    ffma2(acc[i][1], h2.x, wa0.y);
                    ffma2(acc[i][2], h2.x, wb0.x);
                    ffma2(acc[i][3], h2.x, wb0.y);
                    ffma2(acc[i][0], h2.y, wa1.x);
                    ffma2(acc[i][1], h2.y, wa1.y);
                    ffma2(acc[i][2], h2.y, wb1.x);
                    ffma2(acc[i][3], h2.y, wb1.y);
                }
            }
            // cross-ks reduction: lanes (ks in bits 3,4 of lane id)
#pragma unroll
            for (int i = 0; i < 4; i++)
#pragma unroll
                for (int g = 0; g < 4; g++) {
                    float2 u = unpack2(acc[i][g]);
                    float v = u.x + u.y;
                    v += __shfl_xor_sync(0xffffffffu, v, 8);
                    v += __shfl_xor_sync(0xffffffffu, v, 16);
                    af[i][g] = v;
                }
        }

        if (ks == 0) {
#pragma unroll
            for (int i = 0; i < 4; i++) {
                int b = w * 4 + i;
                float p0 = xcur[i][0], p1 = xcur[i][1], p2 = xcur[i][2], p3 = xcur[i][3];
                if (s > 0) { p0 += af[i][0]; p1 += af[i][1]; p2 += af[i][2]; p3 += af[i][3]; }
                float ig = sigmoidf_(p0);
                float fg = sigmoidf_(p1);
                float gg = tanhf(p2);
                float og = sigmoidf_(p3);
                float c = fg * creg[i] + ig * gg;
                creg[i] = c;
                float h = og * tanhf(c);
                int j = j0 + c4;
                g_hbuf[(size_t)(((par ^ 1) * 2 + dir) * BB + b) * HH + j] = h;
                hout[(size_t)(t * BB + b) * 1024 + dir * 512 + j] = h;
            }
            // prefetch xp for next step; DRAM latency hides in the barrier wait
            if (s + 1 < TT) {
                int tn2 = dir ? (TT - 2 - s) : (s + 1);
#pragma unroll
                for (int i = 0; i < 4; i++) {
                    int b = w * 4 + i;
                    const float* xr = xp + (size_t)(tn2 * BB + b) * NG + dir * 2048 + j0 + c4;
                    xcur[i][0] = xr[0];
                    xcur[i][1] = xr[512];
                    xcur[i][2] = xr[1024];
                    xcur[i][3] = xr[1536];
                }
            }
        }
        grid_barrier(dir);
    }
}

// ---------------- emission features: feats = h1 @ lin_w^T + lin_b ----------------
__global__ __launch_bounds__(256) void k_feats(
    const float* __restrict__ h1, const float* __restrict__ lin_w,
    const float* __restrict__ lin_b, float* __restrict__ feats)
{
    extern __shared__ float s[];  // [1024][32] transposed lin_w
    int tid = threadIdx.x;
    for (int i = tid; i < 32 * 1024; i += 256) {
        int c = i & 31, k = i >> 5;
        s[k * 32 + c] = lin_w[c * 1024 + k];
    }
    float bias = lin_b[tid & 31];
    __syncthreads();
    int warp = tid >> 5, lane = tid & 31;
    int rows = TB / gridDim.x;
    int r0 = blockIdx.x * rows;
    for (int r = r0 + warp; r < r0 + rows; r += 8) {
        const float* x = h1 + (size_t)r * 1024;
        float acc = 0.0f;
        for (int k0 = 0; k0 < 1024; k0 += 32) {
            float xv = x[k0 + lane];
#pragma unroll
            for (int kk = 0; kk < 32; kk++) {
                float xs = __shfl_sync(0xffffffffu, xv, kk);
                acc += xs * s[(k0 + kk) * 32 + lane];
            }
        }
        feats[(size_t)r * 32 + lane] = acc + bias;
    }
}

// ---------------- CRF forward (one warp per batch, lane = tag) ----------------
__global__ __launch_bounds__(32) void k_crf(
    const float* __restrict__ feats, const float* __restrict__ trans,
    const int* __restrict__ tokens, float* __restrict__ logz)
{
    __shared__ float s_tr[32 * 33];
    int lane = threadIdx.x;
    for (int i = lane; i < 1024; i += 32)
        s_tr[(i >> 5) * 33 + (i & 31)] = trans[i];
    __syncwarp();
    int b = blockIdx.x;

    float alpha = (lane == STARTT) ? 0.0f : NEGV;
    for (int t = 0; t < TT; t++) {
        float emit = feats[(size_t)(t * BB + b) * 32 + lane];
        int m = tokens[t * BB + b] > 0;
        float v[32];
        float mx = -3.4e38f;
#pragma unroll
        for (int k = 0; k < 32; k++) {
            float ak = __shfl_sync(0xffffffffu, alpha, k);
            v[k] = ak + s_tr[lane * 33 + k];
            mx = fmaxf(mx, v[k]);
        }
        float ssum = 0.0f;
#pragma unroll
        for (int k = 0; k < 32; k++) ssum += __expf(v[k] - mx);
        float nv = mx + __logf(ssum) + emit;
        alpha = m ? nv : alpha;
    }
    float val = alpha + s_tr[ENDT * 33 + lane];
    float mx = val;
#pragma unroll
    for (int o = 16; o; o >>= 1) mx = fmaxf(mx, __shfl_xor_sync(0xffffffffu, mx, o));
    float ss = __expf(val - mx);
#pragma unroll
    for (int o = 16; o; o >>= 1) ss += __shfl_xor_sync(0xffffffffu, ss, o);
    if (lane == 0) logz[b] = mx + __logf(ss);
}

// ---------------- gold score + final reduction ----------------
__global__ void k_final(
    const int* __restrict__ tags, const int* __restrict__ tokens,
    const float* __restrict__ trans, const float* __restrict__ feats,
    const float* __restrict__ logz, const int* __restrict__ lengths,
    float* __restrict__ out)
{
    __shared__ float red[BB];
    int b = threadIdx.x;
    float gold = 0.0f;
    int prev = STARTT;
    for (int t = 0; t < TT; t++) {
        int cur = tags[t * BB + b];
        float m = tokens[t * BB + b] > 0 ? 1.0f : 0.0f;
        gold += m * (trans[cur * 32 + prev] + feats[(size_t)(t * BB + b) * 32 + cur]);
        prev = cur;
    }
    gold += trans[ENDT * 32 + prev];
    red[b] = (logz[b] - gold) / (float)lengths[b];
    __syncthreads();
    if (b == 0) {
        float s = 0.0f;
        for (int i = 0; i < BB; i++) s += red[i];
        out[0] = s;
    }
}

// ---------------- launch ----------------
extern "C" void kernel_launch(void* const* d_in, const int* in_sizes, int n_in,
                              void* d_out, int out_size)
{
    const int*   tokens = (const int*)d_in[0];
    const int*   tags   = (const int*)d_in[1];
    const int*   lens   = (const int*)d_in[2];
    const float* embed  = (const float*)d_in[3];
    const float* wih0   = (const float*)d_in[4];
    const float* whh0   = (const float*)d_in[5];
    const float* b0     = (const float*)d_in[6];
    const float* wih1   = (const float*)d_in[7];
    const float* whh1   = (const float*)d_in[8];
    const float* b1     = (const float*)d_in[9];
    const float* lin_w  = (const float*)d_in[10];
    const float* lin_b  = (const float*)d_in[11];
    const float* trans  = (const float*)d_in[12];
    float* out = (float*)d_out;

    void *p;
    cudaGetSymbolAddress(&p, g_xp);    float* xp    = (float*)p;
    cudaGetSymbolAddress(&p, g_h0);    float* h0    = (float*)p;
    cudaGetSymbolAddress(&p, g_h1);    float* h1    = (float*)p;
    cudaGetSymbolAddress(&p, g_feats); float* feats = (float*)p;
    cudaGetSymbolAddress(&p, g_logz);  float* logz  = (float*)p;

    const int LSTM_SMEM = 32768 * 4 + 2 * 4 * WSTRIDE * 16 + 128;  // 196992 B
    cudaFuncSetAttribute(k_lstm, cudaFuncAttributeMaxDynamicSharedMemorySize, LSTM_SMEM);
    cudaFuncSetAttribute(k_feats, cudaFuncAttributeMaxDynamicSharedMemorySize, 131072);

    dim3 gg(NG / 128, TB / 128);   // (32, 128)

    // layer 0
    k_gemm<EE, true><<<gg, 512>>>(embed, tokens, wih0, b0, xp);
    k_lstm<<<128, 512, LSTM_SMEM>>>(xp, whh0, h0);

    // layer 1
    k_gemm<1024, false><<<gg, 512>>>(h0, tokens, wih1, b1, xp);
    k_lstm<<<128, 512, LSTM_SMEM>>>(xp, whh1, h1);

    // emissions
    k_feats<<<128, 256, 131072>>>(h1, lin_w, lin_b, feats);

    // CRF partition function
    k_crf<<<BB, 32>>>(feats, trans, tokens, logz);

    // gold + loss
    k_final<<<1, BB>>>(tags, tokens, trans, feats, logz, lens, out);
}

// round 10
// speedup vs baseline: 1.3868x; 1.3868x over previous
#include <cuda_runtime.h>
#include <cuda_bf16.h>
#include <cstdint>

typedef unsigned long long ull;

// ---------------- problem constants ----------------
#define TT   256
#define BB   64
#define EE   512
#define HH   512
#define KK   32
#define TB   (TT*BB)        // 16384
#define NG   4096           // 2 dirs * 4H gate columns
#define STARTT 30
#define ENDT   31
#define NEGV  (-100000.0f)

#define HBYTES  (BB*HH*4)   // 131072
#define CHUNKB  8192        // 4 rows * 512 * 4B

// ---------------- device scratch (static, no cudaMalloc) ----------------
__device__ float g_xp[(size_t)TB * NG];        // reused by both layers
__device__ float g_h0[(size_t)TB * 1024];      // layer0 output (fwd|bwd)
__device__ float g_h1[(size_t)TB * 1024];      // layer1 output
__device__ float g_feats[(size_t)TB * KK];     // emissions
__device__ float g_hbuf[2 * 2 * BB * HH];      // [parity][dir][b][j]
__device__ float g_logz[BB];

// per-direction grid barrier state
__device__ unsigned g_cnt2[2] = {0, 0};
__device__ unsigned g_gen2[2] = {0, 0};

// ---------------- helpers ----------------
__device__ __forceinline__ void ffma2(ull &d, ull a, ull b) {
    asm("fma.rn.f32x2 %0, %1, %2, %0;" : "+l"(d) : "l"(a), "l"(b));
}
__device__ __forceinline__ float2 unpack2(ull v) {
    float2 r;
    asm("mov.b64 {%0, %1}, %2;" : "=f"(r.x), "=f"(r.y) : "l"(v));
    return r;
}
__device__ __forceinline__ ull pk2(float lo, float hi) {
    ull v;
    asm("mov.b64 %0, {%1,%2};" : "=l"(v) : "f"(lo), "f"(hi));
    return v;
}
// overflow-safe fast sigmoid/tanh (rel err ~1e-6 << 1e-3 tolerance)
__device__ __forceinline__ float sigf_(float x) { return 1.0f / (1.0f + __expf(-x)); }
__device__ __forceinline__ float tanhf_(float x) {
    float e = __expf(-2.0f * fabsf(x));          // e in (0,1], no overflow
    float r = (1.0f - e) / (1.0f + e);
    return copysignf(r, x);
}
__device__ __forceinline__ float sel4(float a, float b, float c, float d, int k) {
    return (k == 0) ? a : ((k == 1) ? b : ((k == 2) ? c : d));
}

__device__ __forceinline__ uint32_t s2u(const void* p) {
    uint32_t a;
    asm("{ .reg .u64 t; cvta.to.shared.u64 t, %1; cvt.u32.u64 %0, t; }" : "=r"(a) : "l"(p));
    return a;
}
__device__ __forceinline__ void mwait(uint32_t mbar, uint32_t phase) {
    asm volatile(
        "{\n\t.reg .pred P;\n"
        "W%=:\n\t"
        "mbarrier.try_wait.parity.acquire.cta.shared::cta.b64 P, [%0], %1, 0x989680;\n\t"
        "@P bra D%=;\n\t"
        "bra W%=;\n"
        "D%=:\n\t}"
        :: "r"(mbar), "r"(phase) : "memory");
}

__device__ __forceinline__ void grid_barrier(int dir) {
    __syncthreads();
    if (threadIdx.x == 0) {
        __threadfence();
        unsigned my = *((volatile unsigned*)&g_gen2[dir]);
        if (atomicAdd(&g_cnt2[dir], 1u) == 63u) {
            g_cnt2[dir] = 0;
            __threadfence();
            *((volatile unsigned*)&g_gen2[dir]) = my + 1;
        } else {
            while (*((volatile unsigned*)&g_gen2[dir]) == my) { }
        }
        __threadfence();
    }
    __syncthreads();
}

// ---------------- SGEMM: C[16384][4096] = A[M][KD]*Bw[4096][KD]^T + bias ------
// 128x128 tile, 512 threads, f32x2. Loaders pack k-pairs in registers (STS.64,
// conflict-free 4*kp banking). Bs consumer XOR-swizzled -> conflict-free LDS.128.
template<int KD, bool GATHER>
__global__ __launch_bounds__(512) void k_gemm(
    const float* __restrict__ A, const int* __restrict__ tok,
    const float* __restrict__ Bw, const float* __restrict__ bias,
    float* __restrict__ C)
{
    __shared__ ull As[8 * 130];
    __shared__ ull Bs[8 * 130];
    int tid = threadIdx.x;
    int n0 = blockIdx.x * 128, m0 = blockIdx.y * 128;
    int tn = tid & 15, tm = tid >> 4;

    int kp = tid & 7, rr = tid >> 3;   // rr 0..63
    const float* aro[2];
    const float* bro[2];
    int sA[2], sB[2];
#pragma unroll
    for (int i = 0; i < 2; i++) {
        int r = rr + 64 * i;
        aro[i] = (GATHER ? A + (size_t)tok[m0 + r] * KD
                         : A + (size_t)(m0 + r) * KD) + 2 * kp;
        bro[i] = Bw + (size_t)(n0 + r) * KD + 2 * kp;
        sA[i] = kp * 130 + r;
        int t8 = r >> 3, j = (r >> 1) & 3, sw = (r >> 4) & 3;
        sB[i] = kp * 130 + (t8 * 4 + (j ^ sw)) * 2 + (r & 1);
    }

    float bb[8];
#pragma unroll
    for (int j = 0; j < 8; j++) bb[j] = bias[n0 + tn * 8 + j];

    ull acc[4][8];
#pragma unroll
    for (int i = 0; i < 4; i++)
#pragma unroll
        for (int j = 0; j < 8; j++) acc[i][j] = 0ull;

    float2 pa[2], pb[2];
#pragma unroll
    for (int i = 0; i < 2; i++) { pa[i] = *(const float2*)aro[i]; pb[i] = *(const float2*)bro[i]; }

    int swc = (tn >> 1) & 3;

    for (int k0 = 0; k0 < KD; k0 += 16) {
#pragma unroll
        for (int i = 0; i < 2; i++) {
            As[sA[i]] = pk2(pa[i].x, pa[i].y);
            Bs[sB[i]] = pk2(pb[i].x, pb[i].y);
        }
        __syncthreads();
        if (k0 + 16 < KD) {
#pragma unroll
            for (int i = 0; i < 2; i++) {
                pa[i] = *(const float2*)(aro[i] + k0 + 16);
                pb[i] = *(const float2*)(bro[i] + k0 + 16);
            }
        }
#pragma unroll
        for (int k2 = 0; k2 < 8; k2++) {
            ull a2[4], b2[8];
            {
                ulonglong2 v0 = *(const ulonglong2*)&As[k2 * 130 + tm * 4];
                ulonglong2 v1 = *(const ulonglong2*)&As[k2 * 130 + tm * 4 + 2];
                a2[0] = v0.x; a2[1] = v0.y; a2[2] = v1.x; a2[3] = v1.y;
            }
#pragma unroll
            for (int j = 0; j < 4; j++) {
                ulonglong2 v = *(const ulonglong2*)&Bs[k2 * 130 + (tn * 4 + (j ^ swc)) * 2];
                b2[2 * j] = v.x; b2[2 * j + 1] = v.y;
            }
#pragma unroll
            for (int i = 0; i < 4; i++)
#pragma unroll
                for (int j = 0; j < 8; j++)
                    ffma2(acc[i][j], a2[i], b2[j]);
        }
        __syncthreads();
    }
#pragma unroll
    for (int i = 0; i < 4; i++) {
        int m = m0 + tm * 4 + i;
        float o[8];
#pragma unroll
        for (int j = 0; j < 8; j++) {
            float2 u = unpack2(acc[i][j]);
            o[j] = u.x + u.y + bb[j];
        }
        *(float4*)&C[(size_t)m * NG + n0 + tn * 8]     = make_float4(o[0], o[1], o[2], o[3]);
        *(float4*)&C[(size_t)m * NG + n0 + tn * 8 + 4] = make_float4(o[4], o[5], o[6], o[7]);
    }
}

// ---------------- persistent BiLSTM layer kernel ----------------
// grid = 128 CTAs (1/SM), 512 threads (16 warps, 4/SMSP). CTA c: dir = c>>6,
// owns h-cols j0..j0+7. Warp w owns batch rows w*4..w*4+3 (one 8KB h-chunk,
// own mbarrier). Weights resident in SMEM in two gate-pair planes with the
// per-k-quarter rotation (q2 = (q + 4*ks) & 63). Cross-ks reduction via
// shfl_xor gives every lane all 4 row sums; the LSTM cell tail is then
// distributed one row per ks group (row i -> lanes with ks==i) so all 32
// lanes share the MUFU work (was 8 lanes x 4 rows of software expf/tanhf).
__global__ __launch_bounds__(512) void k_lstm(
    const float* __restrict__ xp,   // [TB][4096]: dir*2048 + gt*512 + j (bias incl)
    const float* __restrict__ whh,  // raw [2][2048][512]
    float* __restrict__ hout)       // [TB][1024]: dir*512 + j
{
    extern __shared__ float sm[];
    float* h_s = sm;                                  // 32768 floats (128KB)
    ulonglong2* wA = (ulonglong2*)(sm + 32768);       // gates 0,1: 2048 slots (32KB)
    ulonglong2* wB = wA + 2048;                       // gates 2,3: 2048 slots (32KB)
    ull* mbar = (ull*)(wB + 2048);                    // 16 mbarriers

    int tid = threadIdx.x, cta = blockIdx.x;
    int dir = cta >> 6, j0 = (cta & 63) * 8;
    int lane = tid & 31, w = tid >> 5;                // 16 warps
    int c4 = lane & 7, ks = (lane >> 3) & 3;

    uint32_t mbar_u = s2u(mbar), hdst_u = s2u(h_s);
    if (tid < 16)
        asm volatile("mbarrier.init.shared.b64 [%0], 1;" :: "r"(mbar_u + tid * 8));

    // stage weights with per-quarter rotation: slot (kq, k2, c4) holds k-pair
    // kq*64 + ((k2 + 4*kq) & 63). Plane A = gates 0,1; plane B = gates 2,3.
    const float* W = whh + (size_t)dir * 2048 * 512;
    for (int f = tid; f < 2048; f += 512) {
        int fc = f & 7, k2 = (f >> 3) & 63, kq = f >> 9;
        int k2r = (k2 + 4 * kq) & 63;
        int k = kq * 128 + k2r * 2;
        int jc = j0 + fc;
        const float* w0 = W + (size_t)jc * 512 + k;            // gate 0 row jc
        ull a0 = pk2(w0[0],                 w0[1]);
        ull a1 = pk2(w0[512 * 512],         w0[512 * 512 + 1]);
        ull b0 = pk2(w0[1024 * 512],        w0[1024 * 512 + 1]);
        ull b1 = pk2(w0[1536 * 512],        w0[1536 * 512 + 1]);
        ulonglong2 va; va.x = a0; va.y = a1;
        ulonglong2 vb; vb.x = b0; vb.y = b1;
        wA[f] = va;
        wB[f] = vb;
    }
    __syncthreads();

    const ulonglong2* wAp = wA + ks * 512 + c4;
    const ulonglong2* wBp = wB + ks * 512 + c4;
    const float* hb = h_s + (w * 4) * 512 + ks * 128;
    int rot = ks * 4;

    int brow = w * 4 + ks;         // this lane's batch row for the cell tail
    float creg = 0.0f;             // cell state for (brow, j0+c4)

    for (int s = 0; s < TT; s++) {
        int t = dir ? (TT - 1 - s) : s;
        int par = s & 1;

        // kick off 16 independent row-chunk copies (producer writes fenced by
        // the per-direction grid barrier at the end of the previous step)
        if (s > 0 && tid < 16) {
            const float* src = g_hbuf + (size_t)(par * 2 + dir) * BB * HH + tid * 2048;
            uint32_t mb = mbar_u + tid * 8;
            asm volatile("mbarrier.arrive.expect_tx.shared.b64 _, [%0], %1;"
                         :: "r"(mb), "r"((uint32_t)CHUNKB));
            asm volatile("cp.async.bulk.shared::cta.global.mbarrier::complete_tx::bytes [%0], [%1], %2, [%3];"
                         :: "r"(hdst_u + (uint32_t)tid * CHUNKB), "l"(src),
                            "r"((uint32_t)CHUNKB), "r"(mb) : "memory");
        }

        // xp for this lane's own row (4 gate values), loaded while TMA flies
        float pg0, pg1, pg2, pg3;
        {
            const float* xr = xp + (size_t)(t * BB + brow) * NG + dir * 2048 + j0 + c4;
            pg0 = xr[0];
            pg1 = xr[512];
            pg2 = xr[1024];
            pg3 = xr[1536];
        }

        if (s > 0) {
            // wait only for THIS warp's row chunk
            mwait(mbar_u + w * 8, (s - 1) & 1);

            ull acc[4][4];
#pragma unroll
            for (int i = 0; i < 4; i++)
#pragma unroll
                for (int g = 0; g < 4; g++) acc[i][g] = 0ull;

#pragma unroll 4
            for (int q = 0; q < 64; q += 2) {
                int q2 = (q + rot) & 63;     // rotated k-pair (matches staged weights)
                ulonglong2 wa0 = wAp[q * 8];
                ulonglong2 wb0 = wBp[q * 8];
                ulonglong2 wa1 = wAp[(q + 1) * 8];
                ulonglong2 wb1 = wBp[(q + 1) * 8];
#pragma unroll
                for (int i = 0; i < 4; i++) {
                    ulonglong2 h2 = *(const ulonglong2*)(hb + i * 512 + q2 * 2);
                    ffma2(acc[i][0], h2.x, wa0.x);
                    ffma2(acc[i][1], h2.x, wa0.y);
                    ffma2(acc[i][2], h2.x, wb0.x);
                    ffma2(acc[i][3], h2.x, wb0.y);
                    ffma2(acc[i][0], h2.y, wa1.x);
                    ffma2(acc[i][1], h2.y, wa1.y);
                    ffma2(acc[i][2], h2.y, wb1.x);
                    ffma2(acc[i][3], h2.y, wb1.y);
                }
            }
            // cross-ks reduction (xor over ks bits) -> every lane holds the
            // full sum for all 4 rows; then pick this lane's own row (ks).
            float af[4][4];
#pragma unroll
            for (int i = 0; i < 4; i++)
#pragma unroll
                for (int g = 0; g < 4; g++) {
                    float2 u = unpack2(acc[i][g]);
                    float v = u.x + u.y;
                    v += __shfl_xor_sync(0xffffffffu, v, 8);
                    v += __shfl_xor_sync(0xffffffffu, v, 16);
                    af[i][g] = v;
                }
            pg0 += sel4(af[0][0], af[1][0], af[2][0], af[3][0], ks);
            pg1 += sel4(af[0][1], af[1][1], af[2][1], af[3][1], ks);
            pg2 += sel4(af[0][2], af[1][2], af[2][2], af[3][2], ks);
            pg3 += sel4(af[0][3], af[1][3], af[2][3], af[3][3], ks);
        }

        // LSTM cell for this lane's (row, column) — all 32 lanes active
        {
            float ig = sigf_(pg0);
            float fg = sigf_(pg1);
            float gg = tanhf_(pg2);
            float og = sigf_(pg3);
            float c = fg * creg + ig * gg;
            creg = c;
            float h = og * tanhf_(c);
            int j = j0 + c4;
            g_hbuf[(size_t)(((par ^ 1) * 2 + dir) * BB + brow) * HH + j] = h;
            hout[(size_t)(t * BB + brow) * 1024 + dir * 512 + j] = h;
        }
        grid_barrier(dir);
    }
}

// ---------------- emission features: feats = h1 @ lin_w^T + lin_b ----------------
__global__ __launch_bounds__(256) void k_feats(
    const float* __restrict__ h1, const float* __restrict__ lin_w,
    const float* __restrict__ lin_b, float* __restrict__ feats)
{
    extern __shared__ float s[];  // [1024][32] transposed lin_w
    int tid = threadIdx.x;
    for (int i = tid; i < 32 * 1024; i += 256) {
        int c = i & 31, k = i >> 5;
        s[k * 32 + c] = lin_w[c * 1024 + k];
    }
    float bias = lin_b[tid & 31];
    __syncthreads();
    int warp = tid >> 5, lane = tid & 31;
    int rows = TB / gridDim.x;
    int r0 = blockIdx.x * rows;
    for (int r = r0 + warp; r < r0 + rows; r += 8) {
        const float* x = h1 + (size_t)r * 1024;
        float acc = 0.0f;
        for (int k0 = 0; k0 < 1024; k0 += 32) {
            float xv = x[k0 + lane];
#pragma unroll
            for (int kk = 0; kk < 32; kk++) {
                float xs = __shfl_sync(0xffffffffu, xv, kk);
                acc += xs * s[(k0 + kk) * 32 + lane];
            }
        }
        feats[(size_t)r * 32 + lane] = acc + bias;
    }
}

// ---------------- CRF forward (one warp per batch, lane = tag) ----------------
__global__ __launch_bounds__(32) void k_crf(
    const float* __restrict__ feats, const float* __restrict__ trans,
    const int* __restrict__ tokens, float* __restrict__ logz)
{
    __shared__ float s_tr[32 * 33];
    int lane = threadIdx.x;
    for (int i = lane; i < 1024; i += 32)
        s_tr[(i >> 5) * 33 + (i & 31)] = trans[i];
    __syncwarp();
    int b = blockIdx.x;

    float alpha = (lane == STARTT) ? 0.0f : NEGV;
    for (int t = 0; t < TT; t++) {
        float emit = feats[(size_t)(t * BB + b) * 32 + lane];
        int m = tokens[t * BB + b] > 0;
        float v[32];
        float mx = -3.4e38f;
#pragma unroll
        for (int k = 0; k < 32; k++) {
            float ak = __shfl_sync(0xffffffffu, alpha, k);
            v[k] = ak + s_tr[lane * 33 + k];
            mx = fmaxf(mx, v[k]);
        }
        float ssum = 0.0f;
#pragma unroll
        for (int k = 0; k < 32; k++) ssum += __expf(v[k] - mx);
        float nv = mx + __logf(ssum) + emit;
        alpha = m ? nv : alpha;
    }
    float val = alpha + s_tr[ENDT * 33 + lane];
    float mx = val;
#pragma unroll
    for (int o = 16; o; o >>= 1) mx = fmaxf(mx, __shfl_xor_sync(0xffffffffu, mx, o));
    float ss = __expf(val - mx);
#pragma unroll
    for (int o = 16; o; o >>= 1) ss += __shfl_xor_sync(0xffffffffu, ss, o);
    if (lane == 0) logz[b] = mx + __logf(ss);
}

// ---------------- gold score + final reduction ----------------
__global__ void k_final(
    const int* __restrict__ tags, const int* __restrict__ tokens,
    const float* __restrict__ trans, const float* __restrict__ feats,
    const float* __restrict__ logz, const int* __restrict__ lengths,
    float* __restrict__ out)
{
    __shared__ float red[BB];
    int b = threadIdx.x;
    float gold = 0.0f;
    int prev = STARTT;
    for (int t = 0; t < TT; t++) {
        int cur = tags[t * BB + b];
        float m = tokens[t * BB + b] > 0 ? 1.0f : 0.0f;
        gold += m * (trans[cur * 32 + prev] + feats[(size_t)(t * BB + b) * 32 + cur]);
        prev = cur;
    }
    gold += trans[ENDT * 32 + prev];
    red[b] = (logz[b] - gold) / (float)lengths[b];
    __syncthreads();
    if (b == 0) {
        float s = 0.0f;
        for (int i = 0; i < BB; i++) s += red[i];
        out[0] = s;
    }
}

// ---------------- launch ----------------
extern "C" void kernel_launch(void* const* d_in, const int* in_sizes, int n_in,
                              void* d_out, int out_size)
{
    const int*   tokens = (const int*)d_in[0];
    const int*   tags   = (const int*)d_in[1];
    const int*   lens   = (const int*)d_in[2];
    const float* embed  = (const float*)d_in[3];
    const float* wih0   = (const float*)d_in[4];
    const float* whh0   = (const float*)d_in[5];
    const float* b0     = (const float*)d_in[6];
    const float* wih1   = (const float*)d_in[7];
    const float* whh1   = (const float*)d_in[8];
    const float* b1     = (const float*)d_in[9];
    const float* lin_w  = (const float*)d_in[10];
    const float* lin_b  = (const float*)d_in[11];
    const float* trans  = (const float*)d_in[12];
    float* out = (float*)d_out;

    void *p;
    cudaGetSymbolAddress(&p, g_xp);    float* xp    = (float*)p;
    cudaGetSymbolAddress(&p, g_h0);    float* h0    = (float*)p;
    cudaGetSymbolAddress(&p, g_h1);    float* h1    = (float*)p;
    cudaGetSymbolAddress(&p, g_feats); float* feats = (float*)p;
    cudaGetSymbolAddress(&p, g_logz);  float* logz  = (float*)p;

    const int LSTM_SMEM = 32768 * 4 + 2 * 2048 * 16 + 128;  // 196736 B
    cudaFuncSetAttribute(k_lstm, cudaFuncAttributeMaxDynamicSharedMemorySize, LSTM_SMEM);
    cudaFuncSetAttribute(k_feats, cudaFuncAttributeMaxDynamicSharedMemorySize, 131072);

    dim3 gg(NG / 128, TB / 128);   // (32, 128)

    // layer 0
    k_gemm<EE, true><<<gg, 512>>>(embed, tokens, wih0, b0, xp);
    k_lstm<<<128, 512, LSTM_SMEM>>>(xp, whh0, h0);

    // layer 1
    k_gemm<1024, false><<<gg, 512>>>(h0, tokens, wih1, b1, xp);
    k_lstm<<<128, 512, LSTM_SMEM>>>(xp, whh1, h1);

    // emissions
    k_feats<<<128, 256, 131072>>>(h1, lin_w, lin_b, feats);

    // CRF partition function
    k_crf<<<BB, 32>>>(feats, trans, tokens, logz);

    // gold + loss
    k_final<<<1, BB>>>(tags, tokens, trans, feats, logz, lens, out);
}

// round 12
// speedup vs baseline: 1.3914x; 1.0033x over previous
#include <cuda_runtime.h>
#include <cuda_bf16.h>
#include <cstdint>

typedef unsigned long long ull;

// ---------------- problem constants ----------------
#define TT   256
#define BB   64
#define EE   512
#define HH   512
#define KK   32
#define TB   (TT*BB)        // 16384
#define NG   4096           // 2 dirs * 4H gate columns
#define STARTT 30
#define ENDT   31
#define NEGV  (-100000.0f)

#define HBYTES  (BB*HH*4)   // 131072
#define CHUNKB  8192        // 4 rows * 512 * 4B

// ---------------- device scratch (static, no cudaMalloc) ----------------
__device__ float g_xp[(size_t)TB * NG];        // reused by both layers
__device__ float g_h0[(size_t)TB * 1024];      // layer0 output (fwd|bwd)
__device__ float g_h1[(size_t)TB * 1024];      // layer1 output
__device__ float g_feats[(size_t)TB * KK];     // emissions
__device__ float g_hbuf[2 * 2 * BB * HH];      // [parity][dir][b][j]
__device__ float g_logz[BB];

// per-direction grid barrier state
__device__ unsigned g_cnt2[2] = {0, 0};
__device__ unsigned g_gen2[2] = {0, 0};

// ---------------- helpers ----------------
__device__ __forceinline__ void ffma2(ull &d, ull a, ull b) {
    asm("fma.rn.f32x2 %0, %1, %2, %0;" : "+l"(d) : "l"(a), "l"(b));
}
__device__ __forceinline__ float2 unpack2(ull v) {
    float2 r;
    asm("mov.b64 {%0, %1}, %2;" : "=f"(r.x), "=f"(r.y) : "l"(v));
    return r;
}
__device__ __forceinline__ ull pk2(float lo, float hi) {
    ull v;
    asm("mov.b64 %0, {%1,%2};" : "=l"(v) : "f"(lo), "f"(hi));
    return v;
}
// overflow-safe fast sigmoid/tanh (rel err ~1e-6 << 1e-3 tolerance)
__device__ __forceinline__ float sigf_(float x) { return 1.0f / (1.0f + __expf(-x)); }
__device__ __forceinline__ float tanhf_(float x) {
    float e = __expf(-2.0f * fabsf(x));          // e in (0,1], no overflow
    float r = (1.0f - e) / (1.0f + e);
    return copysignf(r, x);
}
__device__ __forceinline__ float sel4(float a, float b, float c, float d, int k) {
    return (k == 0) ? a : ((k == 1) ? b : ((k == 2) ? c : d));
}

__device__ __forceinline__ uint32_t s2u(const void* p) {
    uint32_t a;
    asm("{ .reg .u64 t; cvta.to.shared.u64 t, %1; cvt.u32.u64 %0, t; }" : "=r"(a) : "l"(p));
    return a;
}
__device__ __forceinline__ void mwait(uint32_t mbar, uint32_t phase) {
    asm volatile(
        "{\n\t.reg .pred P;\n"
        "W%=:\n\t"
        "mbarrier.try_wait.parity.acquire.cta.shared::cta.b64 P, [%0], %1, 0x989680;\n\t"
        "@P bra D%=;\n\t"
        "bra W%=;\n"
        "D%=:\n\t}"
        :: "r"(mbar), "r"(phase) : "memory");
}

__device__ __forceinline__ void grid_barrier(int dir) {
    __syncthreads();
    if (threadIdx.x == 0) {
        __threadfence();
        unsigned my = *((volatile unsigned*)&g_gen2[dir]);
        if (atomicAdd(&g_cnt2[dir], 1u) == 63u) {
            g_cnt2[dir] = 0;
            __threadfence();
            *((volatile unsigned*)&g_gen2[dir]) = my + 1;
        } else {
            while (*((volatile unsigned*)&g_gen2[dir]) == my) { }
        }
        __threadfence();
    }
    __syncthreads();
}

// ---------------- SGEMM: C[16384][4096] = A[M][KD]*Bw[4096][KD]^T + bias ------
// 128x128 tile, 512 threads, f32x2. Loaders pack k-pairs in registers (STS.64,
// conflict-free 4*kp banking). Bs consumer XOR-swizzled -> conflict-free LDS.128.
template<int KD, bool GATHER>
__global__ __launch_bounds__(512) void k_gemm(
    const float* __restrict__ A, const int* __restrict__ tok,
    const float* __restrict__ Bw, const float* __restrict__ bias,
    float* __restrict__ C)
{
    __shared__ ull As[8 * 130];
    __shared__ ull Bs[8 * 130];
    int tid = threadIdx.x;
    int n0 = blockIdx.x * 128, m0 = blockIdx.y * 128;
    int tn = tid & 15, tm = tid >> 4;

    int kp = tid & 7, rr = tid >> 3;   // rr 0..63
    const float* aro[2];
    const float* bro[2];
    int sA[2], sB[2];
#pragma unroll
    for (int i = 0; i < 2; i++) {
        int r = rr + 64 * i;
        aro[i] = (GATHER ? A + (size_t)tok[m0 + r] * KD
                         : A + (size_t)(m0 + r) * KD) + 2 * kp;
        bro[i] = Bw + (size_t)(n0 + r) * KD + 2 * kp;
        sA[i] = kp * 130 + r;
        int t8 = r >> 3, j = (r >> 1) & 3, sw = (r >> 4) & 3;
        sB[i] = kp * 130 + (t8 * 4 + (j ^ sw)) * 2 + (r & 1);
    }

    float bb[8];
#pragma unroll
    for (int j = 0; j < 8; j++) bb[j] = bias[n0 + tn * 8 + j];

    ull acc[4][8];
#pragma unroll
    for (int i = 0; i < 4; i++)
#pragma unroll
        for (int j = 0; j < 8; j++) acc[i][j] = 0ull;

    float2 pa[2], pb[2];
#pragma unroll
    for (int i = 0; i < 2; i++) { pa[i] = *(const float2*)aro[i]; pb[i] = *(const float2*)bro[i]; }

    int swc = (tn >> 1) & 3;

    for (int k0 = 0; k0 < KD; k0 += 16) {
#pragma unroll
        for (int i = 0; i < 2; i++) {
            As[sA[i]] = pk2(pa[i].x, pa[i].y);
            Bs[sB[i]] = pk2(pb[i].x, pb[i].y);
        }
        __syncthreads();
        if (k0 + 16 < KD) {
#pragma unroll
            for (int i = 0; i < 2; i++) {
                pa[i] = *(const float2*)(aro[i] + k0 + 16);
                pb[i] = *(const float2*)(bro[i] + k0 + 16);
            }
        }
#pragma unroll
        for (int k2 = 0; k2 < 8; k2++) {
            ull a2[4], b2[8];
            {
                ulonglong2 v0 = *(const ulonglong2*)&As[k2 * 130 + tm * 4];
                ulonglong2 v1 = *(const ulonglong2*)&As[k2 * 130 + tm * 4 + 2];
                a2[0] = v0.x; a2[1] = v0.y; a2[2] = v1.x; a2[3] = v1.y;
            }
#pragma unroll
            for (int j = 0; j < 4; j++) {
                ulonglong2 v = *(const ulonglong2*)&Bs[k2 * 130 + (tn * 4 + (j ^ swc)) * 2];
                b2[2 * j] = v.x; b2[2 * j + 1] = v.y;
            }
#pragma unroll
            for (int i = 0; i < 4; i++)
#pragma unroll
                for (int j = 0; j < 8; j++)
                    ffma2(acc[i][j], a2[i], b2[j]);
        }
        __syncthreads();
    }
#pragma unroll
    for (int i = 0; i < 4; i++) {
        int m = m0 + tm * 4 + i;
        float o[8];
#pragma unroll
        for (int j = 0; j < 8; j++) {
            float2 u = unpack2(acc[i][j]);
            o[j] = u.x + u.y + bb[j];
        }
        *(float4*)&C[(size_t)m * NG + n0 + tn * 8]     = make_float4(o[0], o[1], o[2], o[3]);
        *(float4*)&C[(size_t)m * NG + n0 + tn * 8 + 4] = make_float4(o[4], o[5], o[6], o[7]);
    }
}

// ---------------- persistent BiLSTM layer kernel ----------------
// grid = 128 CTAs (1/SM), 512 threads (16 warps, 4/SMSP). CTA c: dir = c>>6,
// owns h-cols j0..j0+7. Warp w owns batch rows w*4..w*4+3 (one 8KB h-chunk,
// own mbarrier). Weights resident in SMEM in two gate-pair planes with the
// per-k-quarter rotation (q2 = (q + 4*ks) & 63). Cross-ks reduction via
// shfl_xor gives every lane all 4 row sums; the LSTM cell tail is then
// distributed one row per ks group (row i -> lanes with ks==i) so all 32
// lanes share the MUFU work (was 8 lanes x 4 rows of software expf/tanhf).
__global__ __launch_bounds__(512) void k_lstm(
    const float* __restrict__ xp,   // [TB][4096]: dir*2048 + gt*512 + j (bias incl)
    const float* __restrict__ whh,  // raw [2][2048][512]
    float* __restrict__ hout)       // [TB][1024]: dir*512 + j
{
    extern __shared__ float sm[];
    float* h_s = sm;                                  // 32768 floats (128KB)
    ulonglong2* wA = (ulonglong2*)(sm + 32768);       // gates 0,1: 2048 slots (32KB)
    ulonglong2* wB = wA + 2048;                       // gates 2,3: 2048 slots (32KB)
    ull* mbar = (ull*)(wB + 2048);                    // 16 mbarriers

    int tid = threadIdx.x, cta = blockIdx.x;
    int dir = cta >> 6, j0 = (cta & 63) * 8;
    int lane = tid & 31, w = tid >> 5;                // 16 warps
    int c4 = lane & 7, ks = (lane >> 3) & 3;

    uint32_t mbar_u = s2u(mbar), hdst_u = s2u(h_s);
    if (tid < 16)
        asm volatile("mbarrier.init.shared.b64 [%0], 1;" :: "r"(mbar_u + tid * 8));

    // stage weights with per-quarter rotation: slot (kq, k2, c4) holds k-pair
    // kq*64 + ((k2 + 4*kq) & 63). Plane A = gates 0,1; plane B = gates 2,3.
    const float* W = whh + (size_t)dir * 2048 * 512;
    for (int f = tid; f < 2048; f += 512) {
        int fc = f & 7, k2 = (f >> 3) & 63, kq = f >> 9;
        int k2r = (k2 + 4 * kq) & 63;
        int k = kq * 128 + k2r * 2;
        int jc = j0 + fc;
        const float* w0 = W + (size_t)jc * 512 + k;            // gate 0 row jc
        ull a0 = pk2(w0[0],                 w0[1]);
        ull a1 = pk2(w0[512 * 512],         w0[512 * 512 + 1]);
        ull b0 = pk2(w0[1024 * 512],        w0[1024 * 512 + 1]);
        ull b1 = pk2(w0[1536 * 512],        w0[1536 * 512 + 1]);
        ulonglong2 va; va.x = a0; va.y = a1;
        ulonglong2 vb; vb.x = b0; vb.y = b1;
        wA[f] = va;
        wB[f] = vb;
    }
    __syncthreads();

    const ulonglong2* wAp = wA + ks * 512 + c4;
    const ulonglong2* wBp = wB + ks * 512 + c4;
    const float* hb = h_s + (w * 4) * 512 + ks * 128;
    int rot = ks * 4;

    int brow = w * 4 + ks;         // this lane's batch row for the cell tail
    float creg = 0.0f;             // cell state for (brow, j0+c4)

    for (int s = 0; s < TT; s++) {
        int t = dir ? (TT - 1 - s) : s;
        int par = s & 1;

        // kick off 16 independent row-chunk copies (producer writes fenced by
        // the per-direction grid barrier at the end of the previous step)
        if (s > 0 && tid < 16) {
            const float* src = g_hbuf + (size_t)(par * 2 + dir) * BB * HH + tid * 2048;
            uint32_t mb = mbar_u + tid * 8;
            asm volatile("mbarrier.arrive.expect_tx.shared.b64 _, [%0], %1;"
                         :: "r"(mb), "r"((uint32_t)CHUNKB));
            asm volatile("cp.async.bulk.shared::cta.global.mbarrier::complete_tx::bytes [%0], [%1], %2, [%3];"
                         :: "r"(hdst_u + (uint32_t)tid * CHUNKB), "l"(src),
                            "r"((uint32_t)CHUNKB), "r"(mb) : "memory");
        }

        // xp for this lane's own row (4 gate values), loaded while TMA flies
        float pg0, pg1, pg2, pg3;
        {
            const float* xr = xp + (size_t)(t * BB + brow) * NG + dir * 2048 + j0 + c4;
            pg0 = xr[0];
            pg1 = xr[512];
            pg2 = xr[1024];
            pg3 = xr[1536];
        }

        if (s > 0) {
            // wait only for THIS warp's row chunk
            mwait(mbar_u + w * 8, (s - 1) & 1);

            ull acc[4][4];
#pragma unroll
            for (int i = 0; i < 4; i++)
#pragma unroll
                for (int g = 0; g < 4; g++) acc[i][g] = 0ull;

#pragma unroll 4
            for (int q = 0; q < 64; q += 2) {
                int q2 = (q + rot) & 63;     // rotated k-pair (matches staged weights)
                ulonglong2 wa0 = wAp[q * 8];
                ulonglong2 wb0 = wBp[q * 8];
                ulonglong2 wa1 = wAp[(q + 1) * 8];
                ulonglong2 wb1 = wBp[(q + 1) * 8];
#pragma unroll
                for (int i = 0; i < 4; i++) {
                    ulonglong2 h2 = *(const ulonglong2*)(hb + i * 512 + q2 * 2);
                    ffma2(acc[i][0], h2.x, wa0.x);
                    ffma2(acc[i][1], h2.x, wa0.y);
                    ffma2(acc[i][2], h2.x, wb0.x);
                    ffma2(acc[i][3], h2.x, wb0.y);
                    ffma2(acc[i][0], h2.y, wa1.x);
                    ffma2(acc[i][1], h2.y, wa1.y);
                    ffma2(acc[i][2], h2.y, wb1.x);
                    ffma2(acc[i][3], h2.y, wb1.y);
                }
            }
            // cross-ks reduction (xor over ks bits) -> every lane holds the
            // full sum for all 4 rows; then pick this lane's own row (ks).
            float af[4][4];
#pragma unroll
            for (int i = 0; i < 4; i++)
#pragma unroll
                for (int g = 0; g < 4; g++) {
                    float2 u = unpack2(acc[i][g]);
                    float v = u.x + u.y;
                    v += __shfl_xor_sync(0xffffffffu, v, 8);
                    v += __shfl_xor_sync(0xffffffffu, v, 16);
                    af[i][g] = v;
                }
            pg0 += sel4(af[0][0], af[1][0], af[2][0], af[3][0], ks);
            pg1 += sel4(af[0][1], af[1][1], af[2][1], af[3][1], ks);
            pg2 += sel4(af[0][2], af[1][2], af[2][2], af[3][2], ks);
            pg3 += sel4(af[0][3], af[1][3], af[2][3], af[3][3], ks);
        }

        // LSTM cell for this lane's (row, column) — all 32 lanes active
        {
            float ig = sigf_(pg0);
            float fg = sigf_(pg1);
            float gg = tanhf_(pg2);
            float og = sigf_(pg3);
            float c = fg * creg + ig * gg;
            creg = c;
            float h = og * tanhf_(c);
            int j = j0 + c4;
            g_hbuf[(size_t)(((par ^ 1) * 2 + dir) * BB + brow) * HH + j] = h;
            hout[(size_t)(t * BB + brow) * 1024 + dir * 512 + j] = h;
        }
        grid_barrier(dir);
    }
}

// ---------------- emission features: feats = h1 @ lin_w^T + lin_b ----------------
__global__ __launch_bounds__(256) void k_feats(
    const float* __restrict__ h1, const float* __restrict__ lin_w,
    const float* __restrict__ lin_b, float* __restrict__ feats)
{
    extern __shared__ float s[];  // [1024][32] transposed lin_w
    int tid = threadIdx.x;
    for (int i = tid; i < 32 * 1024; i += 256) {
        int c = i & 31, k = i >> 5;
        s[k * 32 + c] = lin_w[c * 1024 + k];
    }
    float bias = lin_b[tid & 31];
    __syncthreads();
    int warp = tid >> 5, lane = tid & 31;
    int rows = TB / gridDim.x;
    int r0 = blockIdx.x * rows;
    for (int r = r0 + warp; r < r0 + rows; r += 8) {
        const float* x = h1 + (size_t)r * 1024;
        float acc = 0.0f;
        for (int k0 = 0; k0 < 1024; k0 += 32) {
            float xv = x[k0 + lane];
#pragma unroll
            for (int kk = 0; kk < 32; kk++) {
                float xs = __shfl_sync(0xffffffffu, xv, kk);
                acc += xs * s[(k0 + kk) * 32 + lane];
            }
        }
        feats[(size_t)r * 32 + lane] = acc + bias;
    }
}

// ---------------- CRF forward (one warp per batch, lane = tag) ----------------
__global__ __launch_bounds__(32) void k_crf(
    const float* __restrict__ feats, const float* __restrict__ trans,
    const int* __restrict__ tokens, float* __restrict__ logz)
{
    __shared__ float s_tr[32 * 33];
    int lane = threadIdx.x;
    for (int i = lane; i < 1024; i += 32)
        s_tr[(i >> 5) * 33 + (i & 31)] = trans[i];
    __syncwarp();
    int b = blockIdx.x;

    float alpha = (lane == STARTT) ? 0.0f : NEGV;
    for (int t = 0; t < TT; t++) {
        float emit = feats[(size_t)(t * BB + b) * 32 + lane];
        int m = tokens[t * BB + b] > 0;
        float v[32];
        float mx = -3.4e38f;
#pragma unroll
        for (int k = 0; k < 32; k++) {
            float ak = __shfl_sync(0xffffffffu, alpha, k);
            v[k] = ak + s_tr[lane * 33 + k];
            mx = fmaxf(mx, v[k]);
        }
        float ssum = 0.0f;
#pragma unroll
        for (int k = 0; k < 32; k++) ssum += __expf(v[k] - mx);
        float nv = mx + __logf(ssum) + emit;
        alpha = m ? nv : alpha;
    }
    float val = alpha + s_tr[ENDT * 33 + lane];
    float mx = val;
#pragma unroll
    for (int o = 16; o; o >>= 1) mx = fmaxf(mx, __shfl_xor_sync(0xffffffffu, mx, o));
    float ss = __expf(val - mx);
#pragma unroll
    for (int o = 16; o; o >>= 1) ss += __shfl_xor_sync(0xffffffffu, ss, o);
    if (lane == 0) logz[b] = mx + __logf(ss);
}

// ---------------- gold score + final reduction ----------------
__global__ void k_final(
    const int* __restrict__ tags, const int* __restrict__ tokens,
    const float* __restrict__ trans, const float* __restrict__ feats,
    const float* __restrict__ logz, const int* __restrict__ lengths,
    float* __restrict__ out)
{
    __shared__ float red[BB];
    int b = threadIdx.x;
    float gold = 0.0f;
    int prev = STARTT;
    for (int t = 0; t < TT; t++) {
        int cur = tags[t * BB + b];
        float m = tokens[t * BB + b] > 0 ? 1.0f : 0.0f;
        gold += m * (trans[cur * 32 + prev] + feats[(size_t)(t * BB + b) * 32 + cur]);
        prev = cur;
    }
    gold += trans[ENDT * 32 + prev];
    red[b] = (logz[b] - gold) / (float)lengths[b];
    __syncthreads();
    if (b == 0) {
        float s = 0.0f;
        for (int i = 0; i < BB; i++) s += red[i];
        out[0] = s;
    }
}

// ---------------- launch ----------------
extern "C" void kernel_launch(void* const* d_in, const int* in_sizes, int n_in,
                              void* d_out, int out_size)
{
    const int*   tokens = (const int*)d_in[0];
    const int*   tags   = (const int*)d_in[1];
    const int*   lens   = (const int*)d_in[2];
    const float* embed  = (const float*)d_in[3];
    const float* wih0   = (const float*)d_in[4];
    const float* whh0   = (const float*)d_in[5];
    const float* b0     = (const float*)d_in[6];
    const float* wih1   = (const float*)d_in[7];
    const float* whh1   = (const float*)d_in[8];
    const float* b1     = (const float*)d_in[9];
    const float* lin_w  = (const float*)d_in[10];
    const float* lin_b  = (const float*)d_in[11];
    const float* trans  = (const float*)d_in[12];
    float* out = (float*)d_out;

    void *p;
    cudaGetSymbolAddress(&p, g_xp);    float* xp    = (float*)p;
    cudaGetSymbolAddress(&p, g_h0);    float* h0    = (float*)p;
    cudaGetSymbolAddress(&p, g_h1);    float* h1    = (float*)p;
    cudaGetSymbolAddress(&p, g_feats); float* feats = (float*)p;
    cudaGetSymbolAddress(&p, g_logz);  float* logz  = (float*)p;

    const int LSTM_SMEM = 32768 * 4 + 2 * 2048 * 16 + 128;  // 196736 B
    cudaFuncSetAttribute(k_lstm, cudaFuncAttributeMaxDynamicSharedMemorySize, LSTM_SMEM);
    cudaFuncSetAttribute(k_feats, cudaFuncAttributeMaxDynamicSharedMemorySize, 131072);

    dim3 gg(NG / 128, TB / 128);   // (32, 128)

    // layer 0
    k_gemm<EE, true><<<gg, 512>>>(embed, tokens, wih0, b0, xp);
    k_lstm<<<128, 512, LSTM_SMEM>>>(xp, whh0, h0);

    // layer 1
    k_gemm<1024, false><<<gg, 512>>>(h0, tokens, wih1, b1, xp);
    k_lstm<<<128, 512, LSTM_SMEM>>>(xp, whh1, h1);

    // emissions
    k_feats<<<128, 256, 131072>>>(h1, lin_w, lin_b, feats);

    // CRF partition function
    k_crf<<<BB, 32>>>(feats, trans, tokens, logz);

    // gold + loss
    k_final<<<1, BB>>>(tags, tokens, trans, feats, logz, lens, out);
}